// round 3
// baseline (speedup 1.0000x reference)
#include <cuda_runtime.h>
#include <cstdint>

// SKA: out[n, g*8+c, h, w] = sum_{i,j in 7x7} x_pad[n, g*8+c, h+i, w+j] * w[n, c, i*7+j, h, w]
// Shapes (fixed): x [8,512,96,96] f32, w [8,8,49,96,96] f32, out [8,512,96,96] f32.
//
// Strategy: weights are per-output-pixel (49 unique floats) and only reused across
// the g dimension (64x). So each thread owns ONE f32x2 output pair and caches its
// 49 weight-pairs in 98 registers for the whole g loop. x streams through a
// triple-buffered shared tile (cp.async, zero-filled halos). All math is packed
// fp32x2 (fma.rn.f32x2) for 2x FFMA throughput on sm_103a.

#define N_    8
#define IC    512
#define H_    96
#define W_    96
#define WC    8
#define G_    64
#define KS    7
#define PAD   3
#define HT    8                    // output rows per CTA
#define PAIRS 48                   // f32x2 pairs per row (96/2)
#define NTHR  (PAIRS * HT)         // 384 threads
#define TROWS (HT + 2 * PAD)       // 14 staged rows
#define PITCH 104                  // smem floats per row: 3 zero | 96 data | 5 zero
#define TILE_F (TROWS * PITCH)     // 1456 floats per buffer
#define HW    (H_ * W_)            // 9216

typedef unsigned long long u64;

static __device__ __forceinline__ u64 pack2(float a, float b) {
    u64 r; asm("mov.b64 %0, {%1, %2};" : "=l"(r) : "f"(a), "f"(b)); return r;
}
static __device__ __forceinline__ void unpack2(u64 v, float& a, float& b) {
    asm("mov.b64 {%0, %1}, %2;" : "=f"(a), "=f"(b) : "l"(v));
}
static __device__ __forceinline__ void ffma2(u64& d, u64 a, u64 b) {
    asm("fma.rn.f32x2 %0, %1, %2, %0;" : "+l"(d) : "l"(a), "l"(b));
}
static __device__ __forceinline__ u64 fadd2(u64 a, u64 b) {
    u64 d; asm("add.rn.f32x2 %0, %1, %2;" : "=l"(d) : "l"(a), "l"(b)); return d;
}
// 4-byte cp.async with zero-fill when src_sz == 0
static __device__ __forceinline__ void cp4(uint32_t s, const float* g, int src_sz) {
    asm volatile("cp.async.ca.shared.global [%0], [%1], 4, %2;"
                 :: "r"(s), "l"(g), "r"(src_sz));
}

__global__ __launch_bounds__(NTHR, 1)
void ska_kernel(const float* __restrict__ x, const float* __restrict__ wgt,
                float* __restrict__ out) {
    __shared__ float smem[3 * TILE_F];

    const int tid = threadIdx.x;
    const int ht  = blockIdx.x;   // 0..11
    const int c   = blockIdx.y;   // 0..7
    const int n   = blockIdx.z;   // 0..7
    const int h0  = ht * HT;
    const int r   = tid / PAIRS;  // output row within tile, 0..7
    const int p   = tid % PAIRS;  // pair index, 0..47
    const int h   = h0 + r;
    const int w0  = 2 * p;

    // Zero the left/right halo columns of all 3 buffers (never written again).
    if (tid < 3 * TROWS * 8) {
        int b = tid / (TROWS * 8), rem = tid % (TROWS * 8);
        int row = rem / 8, ci = rem % 8;
        int col = (ci < 3) ? ci : 99 + (ci - 3);
        smem[b * TILE_F + row * PITCH + col] = 0.0f;
    }

    // Cache this pixel-pair's 49 weight pairs in registers (reused for all 64 g).
    const float* wb = wgt + ((size_t)(n * WC + c) * 49) * HW + (size_t)h * W_ + w0;
    u64 Wr[49];
    #pragma unroll
    for (int t = 0; t < 49; t++) Wr[t] = *(const u64*)(wb + (size_t)t * HW);

    const float* xn = x   + (size_t)n * IC * HW;
    float*       on = out + (size_t)n * IC * HW;

    const uint32_t sbase = (uint32_t)__cvta_generic_to_shared(smem);

    // Stage the 14x96 x tile for group g into buffer `buf` (async).
    auto stage = [&](int g, int buf) {
        const float* xc = xn + (size_t)(g * WC + c) * HW;
        const uint32_t sb = sbase + (uint32_t)(buf * TILE_F) * 4u;
        #pragma unroll
        for (int k = 0; k < 4; k++) {
            int idx = tid + k * NTHR;
            if (idx < TROWS * W_) {
                int row = idx / W_;
                int col = idx - row * W_;
                int hr  = h0 - PAD + row;
                int ok  = (hr >= 0 && hr < H_) ? 4 : 0;
                int hrc = hr < 0 ? 0 : (hr >= H_ ? H_ - 1 : hr);
                cp4(sb + (uint32_t)(row * PITCH + 3 + col) * 4u,
                    xc + (size_t)hrc * W_ + col, ok);
            }
        }
        asm volatile("cp.async.commit_group;");
    };

    stage(0, 0);

    for (int g = 0; g < G_; ++g) {
        const int buf = g % 3;
        if (g + 1 < G_) {
            stage(g + 1, (g + 1) % 3);
            asm volatile("cp.async.wait_group 1;");
        } else {
            asm volatile("cp.async.wait_group 0;");
        }
        __syncthreads();
        // Triple buffering: staging touches (g+1)%3, laggards at iter g-1 read
        // (g-1)%3 — disjoint mod 3, so one barrier per iteration suffices.

        const float* tb = smem + buf * TILE_F;
        u64 acc0 = 0ull, acc1 = 0ull;  // two chains to halve FFMA2 latency chain
        #pragma unroll
        for (int i = 0; i < KS; i++) {
            const u64* rp = (const u64*)(tb + (r + i) * PITCH + w0);  // 8B aligned
            u64 U0 = rp[0], U1 = rp[1], U2 = rp[2], U3 = rp[3];
            float f0, f1, f2, f3, f4, f5, f6, f7;
            unpack2(U0, f0, f1); unpack2(U1, f2, f3);
            unpack2(U2, f4, f5); unpack2(U3, f6, f7);
            u64& A = (i & 1) ? acc1 : acc0;
            ffma2(A, U0,            Wr[i * 7 + 0]);
            ffma2(A, pack2(f1, f2), Wr[i * 7 + 1]);
            ffma2(A, U1,            Wr[i * 7 + 2]);
            ffma2(A, pack2(f3, f4), Wr[i * 7 + 3]);
            ffma2(A, U2,            Wr[i * 7 + 4]);
            ffma2(A, pack2(f5, f6), Wr[i * 7 + 5]);
            ffma2(A, U3,            Wr[i * 7 + 6]);
        }
        u64 acc = fadd2(acc0, acc1);
        *(u64*)(on + (size_t)(g * WC + c) * HW + (size_t)h * W_ + w0) = acc;
    }
}

extern "C" void kernel_launch(void* const* d_in, const int* in_sizes, int n_in,
                              void* d_out, int out_size) {
    const float* x = (const float*)d_in[0];
    const float* w = (const float*)d_in[1];
    // x (37,748,736 elems) is larger than w (28,901,376); guard against ordering.
    if (n_in >= 2 && in_sizes[0] < in_sizes[1]) {
        const float* t = x; x = w; w = t;
    }
    float* out = (float*)d_out;
    dim3 grid(H_ / HT, WC, N_);  // (12, 8, 8)
    ska_kernel<<<grid, NTHR>>>(x, w, out);
}

// round 4
// speedup vs baseline: 1.2020x; 1.2020x over previous
#include <cuda_runtime.h>
#include <cstdint>

// SKA: out[n, g*8+c, h, w] = sum_{7x7} x_pad[n, g*8+c, h+i, w+j] * w[n, c, i*7+j, h, w]
// x [8,512,96,96] f32, w [8,8,49,96,96] f32, out [8,512,96,96] f32.
//
// Each thread owns ONE f32x2 output pair, caches its 49 weight pairs in regs for
// all 64 g. x streams through shared memory: double-buffered, 2 channels per
// stage (one barrier per 2 g). Even taps: packed fma.rn.f32x2 on aligned LDS.64
// pairs. Odd taps: scalar FMAs on split halves (splitting a reg pair is free;
// merging is not — no pack MOVs in the hot loop).

#define N_    8
#define IC    512
#define H_    96
#define W_    96
#define WC    8
#define G_    64
#define KS    7
#define PAD   3
#define HT    8
#define PAIRS 48
#define NTHR  (PAIRS * HT)          // 384
#define TROWS (HT + 2 * PAD)        // 14
#define PITCH 104                   // 3 zero | 96 data | 5 zero (floats)
#define TILE_F (TROWS * PITCH)      // 1456 floats per channel slab
#define HW    (H_ * W_)             // 9216
#define CSTR  ((size_t)WC * HW)     // channel stride between g steps

typedef unsigned long long u64;

static __device__ __forceinline__ void ffma2(u64& d, u64 a, u64 b) {
    asm("fma.rn.f32x2 %0, %1, %2, %0;" : "+l"(d) : "l"(a), "l"(b));
}
// Odd tap: lo += xl * w.lo, hi += xh * w.hi. mov.b64 {wl,wh},W is a pair-split
// (register aliasing, no SASS), unlike pack which must build a new pair.
static __device__ __forceinline__ void odd_tap(float& lo, float& hi,
                                               float xl, float xh, u64 w) {
    asm("{\n\t"
        ".reg .f32 wl, wh;\n\t"
        "mov.b64 {wl, wh}, %4;\n\t"
        "fma.rn.f32 %0, %2, wl, %0;\n\t"
        "fma.rn.f32 %1, %3, wh, %1;\n\t"
        "}" : "+f"(lo), "+f"(hi) : "f"(xl), "f"(xh), "l"(w));
}
static __device__ __forceinline__ void unpack2(u64 v, float& a, float& b) {
    asm("mov.b64 {%0, %1}, %2;" : "=f"(a), "=f"(b) : "l"(v));
}
static __device__ __forceinline__ u64 pack2(float a, float b) {
    u64 r; asm("mov.b64 %0, {%1, %2};" : "=l"(r) : "f"(a), "f"(b)); return r;
}
static __device__ __forceinline__ void cp4(uint32_t s, const float* g, int sz) {
    asm volatile("cp.async.ca.shared.global [%0], [%1], 4, %2;"
                 :: "r"(s), "l"(g), "r"(sz));
}

__global__ __launch_bounds__(NTHR, 1)
void ska_kernel(const float* __restrict__ x, const float* __restrict__ wgt,
                float* __restrict__ out) {
    __shared__ float smem[4 * TILE_F];   // 2 buffers x 2 channel slabs

    const int tid = threadIdx.x;
    const int ht  = blockIdx.x;          // 0..11
    const int c   = blockIdx.y;          // 0..7
    const int n   = blockIdx.z;          // 0..7
    const int h0  = ht * HT;
    const int r   = tid / PAIRS;
    const int p   = tid % PAIRS;
    const int h   = h0 + r;
    const int w0  = 2 * p;

    // Zero the left/right halo columns of all 4 slabs (written once, never again).
    for (int z = tid; z < 4 * TROWS * 8; z += NTHR) {
        int b = z / (TROWS * 8), rem = z % (TROWS * 8);
        int row = rem / 8, ci = rem % 8;
        int col = (ci < 3) ? ci : 99 + (ci - 3);
        smem[b * TILE_F + row * PITCH + col] = 0.0f;
    }

    // Register-cache this pixel-pair's 49 weight pairs (reused for all 64 g).
    const float* wb = wgt + ((size_t)(n * WC + c) * 49) * HW + (size_t)h * W_ + w0;
    u64 Wr[49];
    #pragma unroll
    for (int t = 0; t < 49; t++) Wr[t] = *(const u64*)(wb + (size_t)t * HW);

    const float* xn = x   + (size_t)n * IC * HW;
    float*       on = out + (size_t)n * IC * HW;
    const uint32_t sbase = (uint32_t)__cvta_generic_to_shared(smem);

    // Hoisted staging descriptors: each thread stages up to 4 elements/channel.
    uint32_t soff[4];          // smem byte offset within a slab
    const float* gptr[4];      // gmem pointer for g=0, row-clamped
    int gsz[4];                // 4 = copy, 0 = zero-fill (OOB row), -1 = inactive
    #pragma unroll
    for (int k = 0; k < 4; k++) {
        int idx = tid + k * NTHR;
        if (idx < TROWS * W_) {
            int row = idx / W_, col = idx - row * W_;
            int hr  = h0 - PAD + row;
            gsz[k]  = (hr >= 0 && hr < H_) ? 4 : 0;
            int hrc = hr < 0 ? 0 : (hr >= H_ ? H_ - 1 : hr);
            soff[k] = (uint32_t)(row * PITCH + 3 + col) * 4u;
            gptr[k] = xn + (size_t)c * HW + (size_t)hrc * W_ + col;
        } else { gsz[k] = -1; soff[k] = 0; gptr[k] = xn; }
    }

    // Stage channels (2*it, 2*it+1) into buffer `buf`; advance pointers by 2 ch.
    auto stage2 = [&](int buf) {
        #pragma unroll
        for (int cc = 0; cc < 2; cc++) {
            uint32_t sb = sbase + (uint32_t)((buf * 2 + cc) * TILE_F) * 4u;
            #pragma unroll
            for (int k = 0; k < 4; k++)
                if (gsz[k] >= 0)
                    cp4(sb + soff[k], gptr[k] + (size_t)cc * CSTR, gsz[k]);
        }
        asm volatile("cp.async.commit_group;");
        #pragma unroll
        for (int k = 0; k < 4; k++) gptr[k] += 2 * CSTR;
    };

    stage2(0);

    float* op = on + (size_t)c * HW + (size_t)h * W_ + w0;
    const int NIT = G_ / 2;   // 32 pipeline stages
    for (int it = 0; it < NIT; ++it) {
        asm volatile("cp.async.wait_group 0;");
        __syncthreads();
        // Order wait -> SYNC -> stage -> compute: stage writes buf^1 while
        // compute reads buf; the SYNC also proves everyone finished the
        // previous compute on buf^1 before it is overwritten. One barrier / 2 g.
        if (it + 1 < NIT) stage2((it + 1) & 1);

        const int buf = it & 1;
        #pragma unroll
        for (int gg = 0; gg < 2; gg++) {
            const float* tb = smem + (buf * 2 + gg) * TILE_F;
            u64 aP0 = 0ull, aP1 = 0ull;       // packed chains (even taps)
            float sLo = 0.0f, sHi = 0.0f;     // scalar chains (odd taps)
            #pragma unroll
            for (int i = 0; i < KS; i++) {
                const u64* rp = (const u64*)(tb + (r + i) * PITCH + w0); // 8B aligned
                u64 U0 = rp[0], U1 = rp[1], U2 = rp[2], U3 = rp[3];
                float f0, f1, f2, f3, f4, f5, f6, f7;
                unpack2(U0, f0, f1); unpack2(U1, f2, f3);
                unpack2(U2, f4, f5); unpack2(U3, f6, f7);
                u64& A = (i & 1) ? aP1 : aP0;
                ffma2(A, U0, Wr[i * 7 + 0]);
                ffma2(A, U1, Wr[i * 7 + 2]);
                ffma2(A, U2, Wr[i * 7 + 4]);
                ffma2(A, U3, Wr[i * 7 + 6]);
                odd_tap(sLo, sHi, f1, f2, Wr[i * 7 + 1]);
                odd_tap(sLo, sHi, f3, f4, Wr[i * 7 + 3]);
                odd_tap(sLo, sHi, f5, f6, Wr[i * 7 + 5]);
            }
            float p0, p1, q0, q1;
            unpack2(aP0, p0, p1);
            unpack2(aP1, q0, q1);
            *(u64*)op = pack2(p0 + q0 + sLo, p1 + q1 + sHi);
            op += CSTR;
        }
    }
}

extern "C" void kernel_launch(void* const* d_in, const int* in_sizes, int n_in,
                              void* d_out, int out_size) {
    const float* x = (const float*)d_in[0];
    const float* w = (const float*)d_in[1];
    // x (37,748,736 elems) > w (28,901,376); guard against input ordering.
    if (n_in >= 2 && in_sizes[0] < in_sizes[1]) {
        const float* t = x; x = w; w = t;
    }
    float* out = (float*)d_out;
    dim3 grid(H_ / HT, WC, N_);   // (12, 8, 8) = 768 CTAs
    ska_kernel<<<grid, NTHR>>>(x, w, out);
}